// round 3
// baseline (speedup 1.0000x reference)
#include <cuda_runtime.h>

#define BDIM 256
#define HW (56*56)
#define NPLANE (32*256)

__device__ float g_pooled[32 * 256];        // [B, C]
__device__ float g_kern[32 * 256 * 9];      // [plane, 9]

// ---------------- kernel 1: global average pool (8 planes / block) ----------------
__global__ void __launch_bounds__(256) pool_kernel(const float* __restrict__ x) {
    const int p0 = blockIdx.x * 8;
    const float4* xp = reinterpret_cast<const float4*>(x + (size_t)p0 * HW);
    float s[8] = {0.f, 0.f, 0.f, 0.f, 0.f, 0.f, 0.f, 0.f};

    #pragma unroll
    for (int it = 0; it < 3; it++) {
        const int i = threadIdx.x + it * 256;
        #pragma unroll
        for (int p = 0; p < 8; p++) {
            float4 v = xp[i + 784 * p];
            s[p] += (v.x + v.y) + (v.z + v.w);
        }
    }
    if (threadIdx.x < 16) {
        const int i = threadIdx.x + 768;
        #pragma unroll
        for (int p = 0; p < 8; p++) {
            float4 v = xp[i + 784 * p];
            s[p] += (v.x + v.y) + (v.z + v.w);
        }
    }

    #pragma unroll
    for (int o = 16; o; o >>= 1) {
        #pragma unroll
        for (int p = 0; p < 8; p++) s[p] += __shfl_xor_sync(0xffffffffu, s[p], o);
    }
    __shared__ float sh[8][8];
    if ((threadIdx.x & 31) == 0) {
        const int w = threadIdx.x >> 5;
        #pragma unroll
        for (int p = 0; p < 8; p++) sh[w][p] = s[p];
    }
    __syncthreads();
    if (threadIdx.x < 8) {
        float v = 0.f;
        #pragma unroll
        for (int w = 0; w < 8; w++) v += sh[w][threadIdx.x];
        g_pooled[p0 + threadIdx.x] = v * (1.0f / HW);
    }
}

// ---------------- kernel 2: kern = relu(pooled @ Wk^T + bk) ----------------
__global__ void kgen_kernel(const float* __restrict__ Wk, const float* __restrict__ bk) {
    __shared__ float psh[32 * 256];
    for (int i = threadIdx.x; i < 32 * 256; i += BDIM) psh[i] = g_pooled[i];
    __syncthreads();

    const int warp = threadIdx.x >> 5;
    const int lane = threadIdx.x & 31;
    const int o = blockIdx.x * 8 + warp;   // 288 blocks * 8 warps = 2304

    float w[8];
    const float* wr = Wk + (size_t)o * 256;
    #pragma unroll
    for (int i = 0; i < 8; i++) w[i] = wr[lane + 32 * i];
    const float bias = bk[o];

    for (int b = 0; b < 32; b++) {
        const float* pr = psh + b * 256;
        float p = 0.f;
        #pragma unroll
        for (int i = 0; i < 8; i++) p = fmaf(w[i], pr[lane + 32 * i], p);
        #pragma unroll
        for (int off = 16; off; off >>= 1) p += __shfl_xor_sync(0xffffffffu, p, off);
        if (lane == 0) g_kern[b * 2304 + o] = fmaxf(p + bias, 0.f);
    }
}

// ---------------- kernel 3: depthwise 3x3, 2 planes/block, float4 tiles ----------------
// smem per plane: 58 rows x 56 cols; smem row (y+1) = global row y; rows 0,57 zero.
// Thread owns 4 cols x 7 rows of one plane: 1 LDS.128 + 2 LDS.32 per row advance,
// STG.128 streaming stores. Plane order reversed vs pool for L2 temporal locality.
__global__ void __launch_bounds__(256) dconv_kernel(const float* __restrict__ x,
                                                    float* __restrict__ out) {
    const int pair = (NPLANE / 2 - 1) - blockIdx.x;
    const int plane0 = pair * 2;

    __shared__ float s[2][58 * 56];
    __shared__ float kf[2][9];

    const int tid = threadIdx.x;
    if (tid < 18) kf[tid / 9][tid % 9] = g_kern[plane0 * 9 + tid];

    const float4* xp = reinterpret_cast<const float4*>(x + (size_t)plane0 * HW);
    float4* s0 = reinterpret_cast<float4*>(&s[0][56]);
    float4* s1 = reinterpret_cast<float4*>(&s[1][56]);
    #pragma unroll
    for (int it = 0; it < 4; it++) {
        const int i = tid + it * 256;
        if (i < 784) { s0[i] = xp[i]; s1[i] = xp[i + 784]; }
    }
    // zero halo rows 0 and 57 for both planes: 4 x 14 float4
    if (tid < 56) {
        const int p = tid / 28, r = (tid % 28) / 14, j = tid % 14;
        reinterpret_cast<float4*>(&s[p][r * 57 * 56])[j] = make_float4(0.f, 0.f, 0.f, 0.f);
    }
    __syncthreads();

    if (tid >= 224) return;                    // no further barriers
    const int pl = tid / 112;
    const int u  = tid % 112;
    const int cg = u % 14;                     // column group
    const int rg = u / 14;                     // row group (0..7)
    const int xc = cg * 4;
    const int y0 = rg * 7;

    const float k0 = kf[pl][0], k1 = kf[pl][1], k2 = kf[pl][2];
    const float k3 = kf[pl][3], k4 = kf[pl][4], k5 = kf[pl][5];
    const float k6 = kf[pl][6], k7 = kf[pl][7], k8 = kf[pl][8];

    const bool lok = cg > 0;
    const bool rok = cg < 13;
    const float* base = &s[pl][0] + y0 * 56 + xc;   // smem row y0 == global row y0-1

    float4 ca = *reinterpret_cast<const float4*>(base);
    float  la = lok ? base[-1] : 0.f;
    float  ra = rok ? base[4]  : 0.f;
    float4 cb = *reinterpret_cast<const float4*>(base + 56);
    float  lb = lok ? base[55] : 0.f;
    float  rb = rok ? base[60] : 0.f;

    float* op = out + (size_t)(plane0 + pl) * HW + y0 * 56 + xc;

    #pragma unroll
    for (int r = 0; r < 7; r++) {
        const float* q = base + (r + 2) * 56;
        float4 cc = *reinterpret_cast<const float4*>(q);
        float  lc = lok ? q[-1] : 0.f;
        float  rc = rok ? q[4]  : 0.f;

        float4 acc;
        acc.x = k0 * la;
        acc.x = fmaf(k1, ca.x, acc.x); acc.x = fmaf(k2, ca.y, acc.x);
        acc.x = fmaf(k3, lb,   acc.x); acc.x = fmaf(k4, cb.x, acc.x);
        acc.x = fmaf(k5, cb.y, acc.x); acc.x = fmaf(k6, lc,   acc.x);
        acc.x = fmaf(k7, cc.x, acc.x); acc.x = fmaf(k8, cc.y, acc.x);

        acc.y = k0 * ca.x;
        acc.y = fmaf(k1, ca.y, acc.y); acc.y = fmaf(k2, ca.z, acc.y);
        acc.y = fmaf(k3, cb.x, acc.y); acc.y = fmaf(k4, cb.y, acc.y);
        acc.y = fmaf(k5, cb.z, acc.y); acc.y = fmaf(k6, cc.x, acc.y);
        acc.y = fmaf(k7, cc.y, acc.y); acc.y = fmaf(k8, cc.z, acc.y);

        acc.z = k0 * ca.y;
        acc.z = fmaf(k1, ca.z, acc.z); acc.z = fmaf(k2, ca.w, acc.z);
        acc.z = fmaf(k3, cb.y, acc.z); acc.z = fmaf(k4, cb.z, acc.z);
        acc.z = fmaf(k5, cb.w, acc.z); acc.z = fmaf(k6, cc.y, acc.z);
        acc.z = fmaf(k7, cc.z, acc.z); acc.z = fmaf(k8, cc.w, acc.z);

        acc.w = k0 * ca.z;
        acc.w = fmaf(k1, ca.w, acc.w); acc.w = fmaf(k2, ra,   acc.w);
        acc.w = fmaf(k3, cb.z, acc.w); acc.w = fmaf(k4, cb.w, acc.w);
        acc.w = fmaf(k5, rb,   acc.w); acc.w = fmaf(k6, cc.z, acc.w);
        acc.w = fmaf(k7, cc.w, acc.w); acc.w = fmaf(k8, rc,   acc.w);

        __stcs(reinterpret_cast<float4*>(op + r * 56), acc);

        ca = cb; la = lb; ra = rb;
        cb = cc; lb = lc; rb = rc;
    }
}

extern "C" void kernel_launch(void* const* d_in, const int* in_sizes, int n_in,
                              void* d_out, int out_size) {
    const float* x  = (const float*)d_in[0];   // [32,256,56,56]
    const float* Wk = (const float*)d_in[1];   // [2304,256]
    const float* bk = (const float*)d_in[2];   // [2304]
    float* out = (float*)d_out;

    pool_kernel<<<NPLANE / 8, BDIM>>>(x);
    kgen_kernel<<<288, BDIM>>>(Wk, bk);
    dconv_kernel<<<NPLANE / 2, BDIM>>>(x, out);
}

// round 4
// speedup vs baseline: 1.2409x; 1.2409x over previous
#include <cuda_runtime.h>

#define BDIM 256
#define HW (56*56)
#define NPLANE (32*256)

__device__ float g_pooled[32 * 256];        // [B, C]
__device__ float g_kern[32 * 256 * 9];      // [plane, 9]

// ---------------- kernel 1: global average pool (4 planes / block) ----------------
__global__ void pool_kernel(const float* __restrict__ x) {
    const int plane0 = blockIdx.x * 4;
    const float4* xp = reinterpret_cast<const float4*>(x + (size_t)plane0 * HW);
    float s0 = 0.f, s1 = 0.f, s2 = 0.f, s3 = 0.f;
    for (int i = threadIdx.x; i < 784; i += BDIM) {
        float4 a = xp[i];
        float4 b = xp[i + 784];
        float4 c = xp[i + 1568];
        float4 d = xp[i + 2352];
        s0 += (a.x + a.y) + (a.z + a.w);
        s1 += (b.x + b.y) + (b.z + b.w);
        s2 += (c.x + c.y) + (c.z + c.w);
        s3 += (d.x + d.y) + (d.z + d.w);
    }
    #pragma unroll
    for (int o = 16; o; o >>= 1) {
        s0 += __shfl_xor_sync(0xffffffffu, s0, o);
        s1 += __shfl_xor_sync(0xffffffffu, s1, o);
        s2 += __shfl_xor_sync(0xffffffffu, s2, o);
        s3 += __shfl_xor_sync(0xffffffffu, s3, o);
    }
    __shared__ float sh[8][4];
    if ((threadIdx.x & 31) == 0) {
        const int w = threadIdx.x >> 5;
        sh[w][0] = s0; sh[w][1] = s1; sh[w][2] = s2; sh[w][3] = s3;
    }
    __syncthreads();
    if (threadIdx.x < 32) {
        const int pl = threadIdx.x & 3;
        const int w  = threadIdx.x >> 2;
        float v = (w < 8) ? sh[w][pl] : 0.f;
        v += __shfl_xor_sync(0xffffffffu, v, 16);
        v += __shfl_xor_sync(0xffffffffu, v, 8);
        v += __shfl_xor_sync(0xffffffffu, v, 4);
        if (w == 0) g_pooled[plane0 + pl] = v * (1.0f / HW);
    }
}

// ---------------- kernel 2: kern = relu(pooled @ Wk^T + bk) ----------------
__global__ void kgen_kernel(const float* __restrict__ Wk, const float* __restrict__ bk) {
    __shared__ float psh[32 * 256];
    for (int i = threadIdx.x; i < 32 * 256; i += BDIM) psh[i] = g_pooled[i];
    __syncthreads();

    const int warp = threadIdx.x >> 5;
    const int lane = threadIdx.x & 31;
    const int o = blockIdx.x * 8 + warp;

    float w[8];
    const float* wr = Wk + (size_t)o * 256;
    #pragma unroll
    for (int i = 0; i < 8; i++) w[i] = wr[lane + 32 * i];
    const float bias = bk[o];

    for (int b = 0; b < 32; b++) {
        const float* pr = psh + b * 256;
        float p = 0.f;
        #pragma unroll
        for (int i = 0; i < 8; i++) p = fmaf(w[i], pr[lane + 32 * i], p);
        #pragma unroll
        for (int off = 16; off; off >>= 1) p += __shfl_xor_sync(0xffffffffu, p, off);
        if (lane == 0) g_kern[b * 2304 + o] = fmaxf(p + bias, 0.f);
    }
}

// ---------------- kernel 3: depthwise 3x3, no smem, rolling global window ----------------
// 2 planes / block, 224 threads. Thread owns 4 cols x 7 rows: per row-advance
// 1 LDG.128 + 2 LDG.32 (L1-served, 3x vertical reuse), ~36 FMA, 1 STG.128 (__stcs).
__global__ void __launch_bounds__(224) dconv_kernel(const float* __restrict__ x,
                                                    float* __restrict__ out) {
    const int tid = threadIdx.x;
    const int pl = tid / 112;
    const int plane = blockIdx.x * 2 + pl;
    const int u  = tid % 112;
    const int cg = u % 14;
    const int rg = u / 14;
    const int xc = cg * 4;
    const int y0 = rg * 7;

    const float* kp = g_kern + plane * 9;
    const float k0 = kp[0], k1 = kp[1], k2 = kp[2];
    const float k3 = kp[3], k4 = kp[4], k5 = kp[5];
    const float k6 = kp[6], k7 = kp[7], k8 = kp[8];

    const bool lok = cg > 0;
    const bool rok = cg < 13;
    const float* xp = x + (size_t)plane * HW + xc;

    float4 ca; float la, ra;
    float4 cb; float lb, rb;

    // row y0-1
    if (rg > 0) {
        const float* p = xp + (y0 - 1) * 56;
        ca = __ldg(reinterpret_cast<const float4*>(p));
        la = lok ? __ldg(p - 1) : 0.f;
        ra = rok ? __ldg(p + 4) : 0.f;
    } else {
        ca = make_float4(0.f, 0.f, 0.f, 0.f); la = 0.f; ra = 0.f;
    }
    // row y0
    {
        const float* p = xp + y0 * 56;
        cb = __ldg(reinterpret_cast<const float4*>(p));
        lb = lok ? __ldg(p - 1) : 0.f;
        rb = rok ? __ldg(p + 4) : 0.f;
    }

    float* op = out + (size_t)plane * HW + y0 * 56 + xc;

    #pragma unroll
    for (int r = 0; r < 7; r++) {
        const int y = y0 + r + 1;
        float4 cc; float lc, rc;
        if (y < 56) {
            const float* p = xp + y * 56;
            cc = __ldg(reinterpret_cast<const float4*>(p));
            lc = lok ? __ldg(p - 1) : 0.f;
            rc = rok ? __ldg(p + 4) : 0.f;
        } else {
            cc = make_float4(0.f, 0.f, 0.f, 0.f); lc = 0.f; rc = 0.f;
        }

        float4 acc;
        acc.x = k0 * la;
        acc.x = fmaf(k1, ca.x, acc.x); acc.x = fmaf(k2, ca.y, acc.x);
        acc.x = fmaf(k3, lb,   acc.x); acc.x = fmaf(k4, cb.x, acc.x);
        acc.x = fmaf(k5, cb.y, acc.x); acc.x = fmaf(k6, lc,   acc.x);
        acc.x = fmaf(k7, cc.x, acc.x); acc.x = fmaf(k8, cc.y, acc.x);

        acc.y = k0 * ca.x;
        acc.y = fmaf(k1, ca.y, acc.y); acc.y = fmaf(k2, ca.z, acc.y);
        acc.y = fmaf(k3, cb.x, acc.y); acc.y = fmaf(k4, cb.y, acc.y);
        acc.y = fmaf(k5, cb.z, acc.y); acc.y = fmaf(k6, cc.x, acc.y);
        acc.y = fmaf(k7, cc.y, acc.y); acc.y = fmaf(k8, cc.z, acc.y);

        acc.z = k0 * ca.y;
        acc.z = fmaf(k1, ca.z, acc.z); acc.z = fmaf(k2, ca.w, acc.z);
        acc.z = fmaf(k3, cb.y, acc.z); acc.z = fmaf(k4, cb.z, acc.z);
        acc.z = fmaf(k5, cb.w, acc.z); acc.z = fmaf(k6, cc.y, acc.z);
        acc.z = fmaf(k7, cc.z, acc.z); acc.z = fmaf(k8, cc.w, acc.z);

        acc.w = k0 * ca.z;
        acc.w = fmaf(k1, ca.w, acc.w); acc.w = fmaf(k2, ra,   acc.w);
        acc.w = fmaf(k3, cb.z, acc.w); acc.w = fmaf(k4, cb.w, acc.w);
        acc.w = fmaf(k5, rb,   acc.w); acc.w = fmaf(k6, cc.z, acc.w);
        acc.w = fmaf(k7, cc.w, acc.w); acc.w = fmaf(k8, rc,   acc.w);

        __stcs(reinterpret_cast<float4*>(op + r * 56), acc);

        ca = cb; la = lb; ra = rb;
        cb = cc; lb = lc; rb = rc;
    }
}

extern "C" void kernel_launch(void* const* d_in, const int* in_sizes, int n_in,
                              void* d_out, int out_size) {
    const float* x  = (const float*)d_in[0];   // [32,256,56,56]
    const float* Wk = (const float*)d_in[1];   // [2304,256]
    const float* bk = (const float*)d_in[2];   // [2304]
    float* out = (float*)d_out;

    pool_kernel<<<NPLANE / 4, BDIM>>>(x);
    kgen_kernel<<<288, BDIM>>>(Wk, bk);
    dconv_kernel<<<NPLANE / 2, 224>>>(x, out);
}